// round 4
// baseline (speedup 1.0000x reference)
#include <cuda_runtime.h>
#include <cuda_bf16.h>

// Problem constants (fixed by the dataset)
#define N_NODES 16384      // B*n = 8*2048
#define K_EDGE  16
#define CIN     64
#define HID     64
#define OUTC    128
#define L6      6
#define KV      384        // 6*64
#define EPS     1e-5f

// ---------------- scratch (device globals; no allocations) ----------------
__device__ float g_V[N_NODES * KV];       // combined edge vectors, row t: [l*64+c]
__device__ float g_Cl[N_NODES * L6];      // per-target coefficient sums
__device__ float g_Y[N_NODES * HID];      // y_pre (before BN1)
__device__ float g_part1[2 * 64 * HID];   // stage-1 BN partials (64 blocks)
__device__ float g_stats1[2 * HID];       // mean, rstd
__device__ float g_part2[2 * 64 * OUTC];
__device__ float g_stats2[2 * OUTC];

// ---------------- K1: per-target edge phase ----------------
// grid = N_NODES blocks, 128 threads.
__global__ __launch_bounds__(128) void k1_edge(
    const float* __restrict__ x, const float* __restrict__ p,
    const int* __restrict__ sid)
{
    __shared__ float s_coef[K_EDGE][8];   // [edge][layer] (padded)
    __shared__ int   s_sid[K_EDGE];

    const int t   = blockIdx.x;
    const int tid = threadIdx.x;

    if (tid < 32) {
        const int lane = tid;
        const int j    = lane & 15;
        const bool act = lane < 16;
        const int e    = t * K_EDGE + j;
        const int s    = sid[e];

        float dx = 0.f, dy = 0.f, dz = 0.f, dis = 0.f;
        if (act) {
            const float px = p[t*3+0], py = p[t*3+1], pz = p[t*3+2];
            dx = p[s*3+0] - px;
            dy = p[s*3+1] - py;
            dz = p[s*3+2] - pz;
            dis = sqrtf(dx*dx + dy*dy + dz*dz);
            dis = fmaxf(dis, 1e-16f);
            s_sid[j] = s;
        }
        // group max of dis (inactive lanes hold 0, all dis >= 1e-16)
        float m = dis;
        #pragma unroll
        for (int off = 16; off; off >>= 1)
            m = fmaxf(m, __shfl_xor_sync(0xffffffffu, m, off));
        const float pr  = 1.1f * m;
        float pdv = act ? (pr - dis) * (pr - dis) : 0.f;
        float ssum = pdv;
        #pragma unroll
        for (int off = 16; off; off >>= 1)
            ssum += __shfl_xor_sync(0xffffffffu, ssum, off);

        if (act) {
            const float w   = pdv / ssum;
            const float inv = 1.f / dis;
            const float c0 = cosf(dx * inv);
            const float c1 = cosf(dy * inv);
            const float c2 = cosf(dz * inv);
            float a[6] = {0.f, 0.f, 0.f, 0.f, 0.f, 0.f};
            a[    (dx > 0.f) ? 1 : 0] = c0 * c0;
            a[2 + ((dy > 0.f) ? 1 : 0)] = c1 * c1;
            a[4 + ((dz > 0.f) ? 1 : 0)] = c2 * c2;
            #pragma unroll
            for (int l = 0; l < 6; l++) s_coef[j][l] = w * a[l];
        }
    }
    __syncthreads();

    if (tid < L6) {
        float cl = 0.f;
        #pragma unroll
        for (int j = 0; j < K_EDGE; j++) cl += s_coef[j][tid];
        g_Cl[t * L6 + tid] = cl;
    }

    // accumulate V: thread (c, grp) owns layers grp*3 .. grp*3+2 for channel c
    const int c   = tid & 63;
    const int grp = tid >> 6;
    const int l0  = grp * 3;
    const float xt = x[t * CIN + c];
    float a0 = 0.f, a1 = 0.f, a2 = 0.f;
    #pragma unroll
    for (int j = 0; j < K_EDGE; j++) {
        const float ev = x[s_sid[j] * CIN + c] - xt;
        a0 = fmaf(s_coef[j][l0    ], ev, a0);
        a1 = fmaf(s_coef[j][l0 + 1], ev, a1);
        a2 = fmaf(s_coef[j][l0 + 2], ev, a2);
    }
    float* vp = g_V + (size_t)t * KV;
    vp[(l0    ) * 64 + c] = a0;
    vp[(l0 + 1) * 64 + c] = a1;
    vp[(l0 + 2) * 64 + c] = a2;
}

// ---------------- K2: y_pre = V @ Wcat + Cl @ lins_b ----------------
// BM=128, BN=64, BK=16, TM=8, TN=4, 256 threads. grid = 128 blocks.
__global__ __launch_bounds__(256) void k2_gemm(
    const float* __restrict__ W2,   // lins_W viewed as (384, 64)
    const float* __restrict__ lb)   // lins_b (6, 64)
{
    __shared__ float As[16][132];
    __shared__ float Bs[16][64];
    __shared__ float sb[6][64];

    const int tid = threadIdx.x;
    const int r0  = blockIdx.x * 128;
    for (int i = tid; i < 384; i += 256) sb[i >> 6][i & 63] = lb[i];

    const int tx = tid & 15;    // 16 col groups of 4
    const int ty = tid >> 4;    // 16 row groups of 8
    float acc[8][4];
    #pragma unroll
    for (int i = 0; i < 8; i++)
        #pragma unroll
        for (int j = 0; j < 4; j++) acc[i][j] = 0.f;

    for (int k0 = 0; k0 < KV; k0 += 16) {
        __syncthreads();
        #pragma unroll
        for (int i = tid; i < 2048; i += 256) {
            const int m = i >> 4, kk = i & 15;
            As[kk][m] = g_V[(size_t)(r0 + m) * KV + k0 + kk];
        }
        #pragma unroll
        for (int i = tid; i < 1024; i += 256) {
            const int r = i >> 6, cc = i & 63;
            Bs[r][cc] = W2[(k0 + r) * 64 + cc];
        }
        __syncthreads();
        #pragma unroll
        for (int kk = 0; kk < 16; kk++) {
            float a[8], b[4];
            float4 a0 = *(const float4*)&As[kk][ty * 8];
            float4 a1 = *(const float4*)&As[kk][ty * 8 + 4];
            a[0]=a0.x; a[1]=a0.y; a[2]=a0.z; a[3]=a0.w;
            a[4]=a1.x; a[5]=a1.y; a[6]=a1.z; a[7]=a1.w;
            float4 b0 = *(const float4*)&Bs[kk][tx * 4];
            b[0]=b0.x; b[1]=b0.y; b[2]=b0.z; b[3]=b0.w;
            #pragma unroll
            for (int i = 0; i < 8; i++)
                #pragma unroll
                for (int j = 0; j < 4; j++)
                    acc[i][j] = fmaf(a[i], b[j], acc[i][j]);
        }
    }

    #pragma unroll
    for (int i = 0; i < 8; i++) {
        const int r = r0 + ty * 8 + i;
        float cl[6];
        #pragma unroll
        for (int l = 0; l < 6; l++) cl[l] = g_Cl[r * L6 + l];
        #pragma unroll
        for (int j = 0; j < 4; j++) {
            const int h = tx * 4 + j;
            float v = acc[i][j];
            #pragma unroll
            for (int l = 0; l < 6; l++) v = fmaf(cl[l], sb[l][h], v);
            g_Y[(size_t)r * HID + h] = v;
        }
    }
}

// ---------------- K3: BN stats over y_pre (64 channels) ----------------
__global__ __launch_bounds__(256) void k3a_stats()
{
    __shared__ float sr[4][64], sr2[4][64];
    const int tid = threadIdx.x;
    const int ch = tid & 63, rg = tid >> 6;
    const int rbase = blockIdx.x * 256;
    float s = 0.f, s2 = 0.f;
    for (int r = rbase + rg; r < rbase + 256; r += 4) {
        const float v = g_Y[(size_t)r * HID + ch];
        s += v; s2 += v * v;
    }
    sr[rg][ch] = s; sr2[rg][ch] = s2;
    __syncthreads();
    if (tid < 64) {
        s  = sr[0][tid] + sr[1][tid] + sr[2][tid] + sr[3][tid];
        s2 = sr2[0][tid] + sr2[1][tid] + sr2[2][tid] + sr2[3][tid];
        g_part1[blockIdx.x * 64 + tid] = s;
        g_part1[4096 + blockIdx.x * 64 + tid] = s2;
    }
}

__global__ void k3b_stats()
{
    const int ch = threadIdx.x;
    float s = 0.f, s2 = 0.f;
    for (int b = 0; b < 64; b++) {
        s  += g_part1[b * 64 + ch];
        s2 += g_part1[4096 + b * 64 + ch];
    }
    const float mean = s * (1.f / N_NODES);
    const float var  = s2 * (1.f / N_NODES) - mean * mean;
    g_stats1[ch] = mean;
    g_stats1[64 + ch] = rsqrtf(var + EPS);
}

// ---------------- K4: out_pre = [x | bnrelu(y_pre)] @ [W1; W2] + b1 + b2 ----
// BM=128, BN=128, BK=16, TM=8, TN=8, 256 threads. grid = 128 blocks.
__global__ __launch_bounds__(256) void k4_gemm(
    const float* __restrict__ x,
    const float* __restrict__ w1,  const float* __restrict__ w2,
    const float* __restrict__ b1w, const float* __restrict__ b2w,
    const float* __restrict__ gam1, const float* __restrict__ bet1,
    float* __restrict__ out)
{
    __shared__ float As[16][132];
    __shared__ float Bs[16][128];
    __shared__ float s_scale[64], s_shift[64];

    const int tid = threadIdx.x;
    const int r0  = blockIdx.x * 128;
    if (tid < 64) {
        const float mean = g_stats1[tid], rstd = g_stats1[64 + tid];
        const float sc = rstd * gam1[tid];
        s_scale[tid] = sc;
        s_shift[tid] = bet1[tid] - mean * sc;
    }

    const int tx = tid & 15;   // 16 col groups of 8
    const int ty = tid >> 4;   // 16 row groups of 8
    float acc[8][8];
    #pragma unroll
    for (int i = 0; i < 8; i++)
        #pragma unroll
        for (int j = 0; j < 8; j++) acc[i][j] = 0.f;

    for (int k0 = 0; k0 < 128; k0 += 16) {
        const bool xhalf = (k0 < 64);
        __syncthreads();
        #pragma unroll
        for (int i = tid; i < 2048; i += 256) {
            const int m = i >> 4, kk = i & 15;
            const int col = k0 + kk;
            float v;
            if (xhalf) {
                v = x[(size_t)(r0 + m) * CIN + col];
            } else {
                const int c = col - 64;
                v = g_Y[(size_t)(r0 + m) * HID + c];
                v = fmaxf(fmaf(v, s_scale[c], s_shift[c]), 0.f);
            }
            As[kk][m] = v;
        }
        #pragma unroll
        for (int i = tid; i < 2048; i += 256) {
            const int r = i >> 7, cc = i & 127;
            const int jrow = k0 + r;
            Bs[r][cc] = xhalf ? w1[jrow * OUTC + cc]
                              : w2[(jrow - 64) * OUTC + cc];
        }
        __syncthreads();
        #pragma unroll
        for (int kk = 0; kk < 16; kk++) {
            float a[8], b[8];
            float4 a0 = *(const float4*)&As[kk][ty * 8];
            float4 a1 = *(const float4*)&As[kk][ty * 8 + 4];
            a[0]=a0.x; a[1]=a0.y; a[2]=a0.z; a[3]=a0.w;
            a[4]=a1.x; a[5]=a1.y; a[6]=a1.z; a[7]=a1.w;
            float4 b0 = *(const float4*)&Bs[kk][tx * 8];
            float4 b1v = *(const float4*)&Bs[kk][tx * 8 + 4];
            b[0]=b0.x; b[1]=b0.y; b[2]=b0.z; b[3]=b0.w;
            b[4]=b1v.x; b[5]=b1v.y; b[6]=b1v.z; b[7]=b1v.w;
            #pragma unroll
            for (int i = 0; i < 8; i++)
                #pragma unroll
                for (int j = 0; j < 8; j++)
                    acc[i][j] = fmaf(a[i], b[j], acc[i][j]);
        }
    }

    #pragma unroll
    for (int i = 0; i < 8; i++) {
        const int r = r0 + ty * 8 + i;
        #pragma unroll
        for (int j = 0; j < 8; j++) {
            const int h = tx * 8 + j;
            out[(size_t)r * OUTC + h] = acc[i][j] + b1w[h] + b2w[h];
        }
    }
}

// ---------------- K5: BN stats over out_pre (128 channels) ----------------
__global__ __launch_bounds__(256) void k5a_stats(const float* __restrict__ out)
{
    __shared__ float sr[2][128], sr2[2][128];
    const int tid = threadIdx.x;
    const int ch = tid & 127, rg = tid >> 7;
    const int rbase = blockIdx.x * 256;
    float s = 0.f, s2 = 0.f;
    for (int r = rbase + rg; r < rbase + 256; r += 2) {
        const float v = out[(size_t)r * OUTC + ch];
        s += v; s2 += v * v;
    }
    sr[rg][ch] = s; sr2[rg][ch] = s2;
    __syncthreads();
    if (tid < 128) {
        s  = sr[0][tid] + sr[1][tid];
        s2 = sr2[0][tid] + sr2[1][tid];
        g_part2[blockIdx.x * 128 + tid] = s;
        g_part2[8192 + blockIdx.x * 128 + tid] = s2;
    }
}

__global__ void k5b_stats()
{
    const int ch = threadIdx.x;
    float s = 0.f, s2 = 0.f;
    for (int b = 0; b < 64; b++) {
        s  += g_part2[b * 128 + ch];
        s2 += g_part2[8192 + b * 128 + ch];
    }
    const float mean = s * (1.f / N_NODES);
    const float var  = s2 * (1.f / N_NODES) - mean * mean;
    g_stats2[ch] = mean;
    g_stats2[128 + ch] = rsqrtf(var + EPS);
}

// ---------------- K6: in-place BN + relu ----------------
__global__ __launch_bounds__(256) void k6_final(
    float* __restrict__ out,
    const float* __restrict__ gam2, const float* __restrict__ bet2)
{
    const int i = blockIdx.x * blockDim.x + threadIdx.x;
    if (i < N_NODES * OUTC) {
        const int ch = i & 127;
        const float mean = g_stats2[ch], rstd = g_stats2[128 + ch];
        const float v = out[i];
        out[i] = fmaxf((v - mean) * rstd * gam2[ch] + bet2[ch], 0.f);
    }
}

// ---------------- launcher ----------------
extern "C" void kernel_launch(void* const* d_in, const int* in_sizes, int n_in,
                              void* d_out, int out_size)
{
    const float* x   = (const float*)d_in[0];
    const float* p   = (const float*)d_in[1];
    const int*   sid = (const int*)d_in[2];
    // d_in[3] = tid_euc (implicitly arange/k grouping; unused)

    // B, n may or may not be passed as scalar inputs; detect via size.
    int o = 4;
    if (n_in >= 16 && in_sizes[4] == 1) o = 6;

    const float* lins_W = (const float*)d_in[o];
    const float* lins_b = (const float*)d_in[o + 1];
    const float* lin1_W = (const float*)d_in[o + 2];
    const float* lin1_b = (const float*)d_in[o + 3];
    const float* lin2_W = (const float*)d_in[o + 4];
    const float* lin2_b = (const float*)d_in[o + 5];
    const float* g1     = (const float*)d_in[o + 6];
    const float* b1     = (const float*)d_in[o + 7];
    const float* g2     = (const float*)d_in[o + 8];
    const float* b2     = (const float*)d_in[o + 9];
    float* out = (float*)d_out;

    k1_edge<<<N_NODES, 128>>>(x, p, sid);
    k2_gemm<<<N_NODES / 128, 256>>>(lins_W, lins_b);
    k3a_stats<<<64, 256>>>();
    k3b_stats<<<1, 64>>>();
    k4_gemm<<<N_NODES / 128, 256>>>(x, lin1_W, lin2_W, lin1_b, lin2_b, g1, b1, out);
    k5a_stats<<<64, 256>>>(out);
    k5b_stats<<<1, 128>>>();
    k6_final<<<(N_NODES * OUTC) / 256, 256>>>(out, g2, b2);
}

// round 5
// speedup vs baseline: 1.2936x; 1.2936x over previous
#include <cuda_runtime.h>
#include <cuda_bf16.h>

// Problem constants (fixed by the dataset)
#define N_NODES 16384      // B*n = 8*2048
#define K_EDGE  16
#define CIN     64
#define HID     64
#define OUTC    128
#define L6      6
#define KV      384        // 6*64
#define EPS     1e-5f

// ---------------- scratch (device globals; no allocations) ----------------
__device__ float g_V[N_NODES * KV];        // combined edge vectors, row t: [l*64+c]
__device__ float g_Cl[N_NODES * L6];       // per-target coefficient sums
__device__ float g_Y[N_NODES * HID];       // y_pre (before BN1)
__device__ float g_part1[2 * 128 * HID];   // per-K2-block BN partials (sum, sumsq)
__device__ float g_part2[2 * 128 * OUTC];  // per-K4-block BN partials

// ---------------- f32x2 helpers (Blackwell packed fp32) ----------------
__device__ __forceinline__ void ffma2(unsigned long long& d,
                                      unsigned long long a,
                                      unsigned long long b) {
    asm("fma.rn.f32x2 %0, %1, %2, %3;" : "=l"(d) : "l"(a), "l"(b), "l"(d));
}
__device__ __forceinline__ float2 unpk(unsigned long long v) {
    unsigned lo, hi;
    asm("mov.b64 {%0,%1}, %2;" : "=r"(lo), "=r"(hi) : "l"(v));
    return make_float2(__uint_as_float(lo), __uint_as_float(hi));
}

// ---------------- K1: per-target edge phase ----------------
// grid = N_NODES/4 blocks, 256 threads (4 targets per block).
__global__ __launch_bounds__(256) void k1_edge(
    const float* __restrict__ x, const float* __restrict__ p,
    const int* __restrict__ sid)
{
    __shared__ float s_coef[4][K_EDGE][8];  // [tgt][edge][layer] (padded to 8)
    __shared__ int   s_sid[4][K_EDGE];

    const int tid  = threadIdx.x;
    const int w    = tid >> 5;
    const int lane = tid & 31;

    if (w < 4) {
        const int t   = blockIdx.x * 4 + w;
        const int j   = lane & 15;
        const bool act = lane < 16;
        const int s   = sid[t * K_EDGE + j];

        float dx = 0.f, dy = 0.f, dz = 0.f, dis = 0.f;
        if (act) {
            const float px = p[t*3+0], py = p[t*3+1], pz = p[t*3+2];
            dx = p[s*3+0] - px;
            dy = p[s*3+1] - py;
            dz = p[s*3+2] - pz;
            dis = fmaxf(sqrtf(dx*dx + dy*dy + dz*dz), 1e-16f);
            s_sid[w][j] = s;
        }
        float m = dis;
        #pragma unroll
        for (int off = 16; off; off >>= 1)
            m = fmaxf(m, __shfl_xor_sync(0xffffffffu, m, off));
        const float pr  = 1.1f * m;
        float pdv = act ? (pr - dis) * (pr - dis) : 0.f;
        float ssum = pdv;
        #pragma unroll
        for (int off = 16; off; off >>= 1)
            ssum += __shfl_xor_sync(0xffffffffu, ssum, off);

        if (act) {
            const float wgt = pdv / ssum;
            const float inv = 1.f / dis;
            const float c0 = cosf(dx * inv);
            const float c1 = cosf(dy * inv);
            const float c2 = cosf(dz * inv);
            float a[6] = {0.f, 0.f, 0.f, 0.f, 0.f, 0.f};
            a[    ((dx > 0.f) ? 1 : 0)] = c0 * c0;
            a[2 + ((dy > 0.f) ? 1 : 0)] = c1 * c1;
            a[4 + ((dz > 0.f) ? 1 : 0)] = c2 * c2;
            #pragma unroll
            for (int l = 0; l < 6; l++) s_coef[w][j][l] = wgt * a[l];
        }
    }
    __syncthreads();

    // Cl sums (24 threads: 4 targets x 6 layers)
    if (tid < 24) {
        const int tw = tid / 6, l = tid - tw * 6;
        float cl = 0.f;
        #pragma unroll
        for (int j = 0; j < K_EDGE; j++) cl += s_coef[tw][j][l];
        g_Cl[(blockIdx.x * 4 + tw) * L6 + l] = cl;
    }

    // V accumulation: 64 threads per target, each thread owns channel c, all 6 layers
    const int grp = tid >> 6;          // target within block
    const int c   = tid & 63;          // channel
    const int t   = blockIdx.x * 4 + grp;
    const float xt = x[t * CIN + c];
    float acc[6] = {0.f, 0.f, 0.f, 0.f, 0.f, 0.f};
    #pragma unroll
    for (int j = 0; j < K_EDGE; j++) {
        const float ev = x[s_sid[grp][j] * CIN + c] - xt;
        const float4 c01 = *(const float4*)&s_coef[grp][j][0];
        const float2 c2  = *(const float2*)&s_coef[grp][j][4];
        acc[0] = fmaf(c01.x, ev, acc[0]);
        acc[1] = fmaf(c01.y, ev, acc[1]);
        acc[2] = fmaf(c01.z, ev, acc[2]);
        acc[3] = fmaf(c01.w, ev, acc[3]);
        acc[4] = fmaf(c2.x,  ev, acc[4]);
        acc[5] = fmaf(c2.y,  ev, acc[5]);
    }
    float* vp = g_V + (size_t)t * KV + c;
    #pragma unroll
    for (int l = 0; l < 6; l++) vp[l * 64] = acc[l];
}

// ---------------- K2: y_pre = V @ Wcat + Cl @ lins_b  (+ BN1 partials) ----
// BM=128, BN=64, BK=16, 256 threads, f32x2 inner loop. grid = 128 blocks.
#define AST2 258
__global__ __launch_bounds__(256) void k2_gemm(
    const float* __restrict__ W2,   // lins_W viewed as (384, 64)
    const float* __restrict__ lb)   // lins_b (6, 64)
{
    __shared__ float Asd[16][AST2];    // A dup: row m at floats 2m,2m+1
    __shared__ float Bsp[16][64];      // B pair-swizzled: h -> jp*32 + tx*2 + lo
    __shared__ float sb[6][64];
    __shared__ float s_m[16][64], s_v[16][64];

    const int tid = threadIdx.x;
    const int r0  = blockIdx.x * 128;
    for (int i = tid; i < 384; i += 256) sb[i >> 6][i & 63] = lb[i];

    const int tx = tid & 15;    // col group of 4
    const int ty = tid >> 4;    // row group of 8
    unsigned long long acc[8][2];
    #pragma unroll
    for (int i = 0; i < 8; i++) { acc[i][0] = 0ULL; acc[i][1] = 0ULL; }

    for (int k0 = 0; k0 < KV; k0 += 16) {
        __syncthreads();
        #pragma unroll
        for (int i = tid; i < 2048; i += 256) {
            const int m = i >> 4, kk = i & 15;
            const float v = g_V[(size_t)(r0 + m) * KV + k0 + kk];
            *(float2*)&Asd[kk][2 * m] = make_float2(v, v);
        }
        #pragma unroll
        for (int i = tid; i < 1024; i += 256) {
            const int r = i >> 6, h = i & 63;
            Bsp[r][((h & 3) >> 1) * 32 + (h >> 2) * 2 + (h & 1)] =
                W2[(k0 + r) * 64 + h];
        }
        __syncthreads();
        #pragma unroll
        for (int kk = 0; kk < 16; kk++) {
            const unsigned long long* ap = (const unsigned long long*)&Asd[kk][0];
            const unsigned long long* bp = (const unsigned long long*)&Bsp[kk][0];
            unsigned long long a[8], b[2];
            #pragma unroll
            for (int i = 0; i < 8; i++) a[i] = ap[ty * 8 + i];
            b[0] = bp[tx];
            b[1] = bp[16 + tx];
            #pragma unroll
            for (int i = 0; i < 8; i++) {
                ffma2(acc[i][0], a[i], b[0]);
                ffma2(acc[i][1], a[i], b[1]);
            }
        }
    }

    float cs[4] = {0.f, 0.f, 0.f, 0.f};
    float cs2[4] = {0.f, 0.f, 0.f, 0.f};
    #pragma unroll
    for (int i = 0; i < 8; i++) {
        const int r = r0 + ty * 8 + i;
        float cl[6];
        #pragma unroll
        for (int l = 0; l < 6; l++) cl[l] = g_Cl[r * L6 + l];
        const float2 v0 = unpk(acc[i][0]);
        const float2 v1 = unpk(acc[i][1]);
        float vv[4] = {v0.x, v0.y, v1.x, v1.y};
        #pragma unroll
        for (int q = 0; q < 4; q++) {
            const int h = tx * 4 + q;
            #pragma unroll
            for (int l = 0; l < 6; l++) vv[q] = fmaf(cl[l], sb[l][h], vv[q]);
            cs[q] += vv[q];
            cs2[q] += vv[q] * vv[q];
        }
        *(float4*)&g_Y[(size_t)r * HID + tx * 4] =
            make_float4(vv[0], vv[1], vv[2], vv[3]);
    }

    #pragma unroll
    for (int q = 0; q < 4; q++) {
        s_m[ty][tx * 4 + q] = cs[q];
        s_v[ty][tx * 4 + q] = cs2[q];
    }
    __syncthreads();
    if (tid < 64) {
        float s = 0.f, s2 = 0.f;
        #pragma unroll
        for (int g = 0; g < 16; g++) { s += s_m[g][tid]; s2 += s_v[g][tid]; }
        g_part1[blockIdx.x * 64 + tid] = s;
        g_part1[8192 + blockIdx.x * 64 + tid] = s2;
    }
}

// ---------------- K4: out_pre = [x | bnrelu(y_pre)] @ [W1; W2] + biases ----
// BM=128, BN=128, BK=16, 256 threads, f32x2. grid = 128 blocks.
__global__ __launch_bounds__(256) void k4_gemm(
    const float* __restrict__ x,
    const float* __restrict__ w1,  const float* __restrict__ w2,
    const float* __restrict__ b1w, const float* __restrict__ b2w,
    const float* __restrict__ gam1, const float* __restrict__ bet1,
    float* __restrict__ out)
{
    __shared__ float Asd[16][AST2];
    __shared__ float Bsp[16][128];
    __shared__ float s_scale[64], s_shift[64], s_bias[128];
    __shared__ float s_red[4][64], s_red2[4][64];
    __shared__ float s_m[16][128], s_v[16][128];

    const int tid = threadIdx.x;
    const int r0  = blockIdx.x * 128;

    // reduce BN1 partials (128 K2 blocks) in-block
    {
        const int ch = tid & 63, q = tid >> 6;
        float s = 0.f, s2 = 0.f;
        #pragma unroll
        for (int b = q * 32; b < q * 32 + 32; b++) {
            s  += g_part1[b * 64 + ch];
            s2 += g_part1[8192 + b * 64 + ch];
        }
        s_red[q][ch] = s; s_red2[q][ch] = s2;
        if (tid < 128) s_bias[tid] = b1w[tid] + b2w[tid];
        __syncthreads();
        if (tid < 64) {
            const float ss  = s_red[0][tid] + s_red[1][tid] + s_red[2][tid] + s_red[3][tid];
            const float ss2 = s_red2[0][tid] + s_red2[1][tid] + s_red2[2][tid] + s_red2[3][tid];
            const float mean = ss * (1.f / (float)N_NODES);
            const float var  = ss2 * (1.f / (float)N_NODES) - mean * mean;
            const float sc = rsqrtf(var + EPS) * gam1[tid];
            s_scale[tid] = sc;
            s_shift[tid] = bet1[tid] - mean * sc;
        }
    }

    const int tx = tid & 15;   // col group of 8
    const int ty = tid >> 4;   // row group of 8
    unsigned long long acc[8][4];
    #pragma unroll
    for (int i = 0; i < 8; i++)
        #pragma unroll
        for (int j = 0; j < 4; j++) acc[i][j] = 0ULL;

    for (int k0 = 0; k0 < 128; k0 += 16) {
        const bool xhalf = (k0 < 64);
        __syncthreads();
        #pragma unroll
        for (int i = tid; i < 2048; i += 256) {
            const int m = i >> 4, kk = i & 15;
            float v;
            if (xhalf) {
                v = x[(size_t)(r0 + m) * CIN + k0 + kk];
            } else {
                const int c = k0 + kk - 64;
                v = g_Y[(size_t)(r0 + m) * HID + c];
                v = fmaxf(fmaf(v, s_scale[c], s_shift[c]), 0.f);
            }
            *(float2*)&Asd[kk][2 * m] = make_float2(v, v);
        }
        #pragma unroll
        for (int i = tid; i < 2048; i += 256) {
            const int r = i >> 7, h = i & 127;
            const float v = xhalf ? w1[(k0 + r) * OUTC + h]
                                  : w2[(k0 + r - 64) * OUTC + h];
            Bsp[r][((h & 7) >> 1) * 32 + (h >> 3) * 2 + (h & 1)] = v;
        }
        __syncthreads();
        #pragma unroll
        for (int kk = 0; kk < 16; kk++) {
            const unsigned long long* ap = (const unsigned long long*)&Asd[kk][0];
            const unsigned long long* bp = (const unsigned long long*)&Bsp[kk][0];
            unsigned long long a[8], b[4];
            #pragma unroll
            for (int i = 0; i < 8; i++) a[i] = ap[ty * 8 + i];
            #pragma unroll
            for (int jp = 0; jp < 4; jp++) b[jp] = bp[jp * 16 + tx];
            #pragma unroll
            for (int i = 0; i < 8; i++)
                #pragma unroll
                for (int jp = 0; jp < 4; jp++)
                    ffma2(acc[i][jp], a[i], b[jp]);
        }
    }

    float cs[8], cs2[8];
    #pragma unroll
    for (int q = 0; q < 8; q++) { cs[q] = 0.f; cs2[q] = 0.f; }
    #pragma unroll
    for (int i = 0; i < 8; i++) {
        const int r = r0 + ty * 8 + i;
        const float2 v0 = unpk(acc[i][0]);
        const float2 v1 = unpk(acc[i][1]);
        const float2 v2 = unpk(acc[i][2]);
        const float2 v3 = unpk(acc[i][3]);
        float vv[8] = {v0.x, v0.y, v1.x, v1.y, v2.x, v2.y, v3.x, v3.y};
        #pragma unroll
        for (int q = 0; q < 8; q++) {
            vv[q] += s_bias[tx * 8 + q];
            cs[q] += vv[q];
            cs2[q] += vv[q] * vv[q];
        }
        float* op = out + (size_t)r * OUTC + tx * 8;
        *(float4*)op       = make_float4(vv[0], vv[1], vv[2], vv[3]);
        *(float4*)(op + 4) = make_float4(vv[4], vv[5], vv[6], vv[7]);
    }

    #pragma unroll
    for (int q = 0; q < 8; q++) {
        s_m[ty][tx * 8 + q] = cs[q];
        s_v[ty][tx * 8 + q] = cs2[q];
    }
    __syncthreads();
    if (tid < 128) {
        float s = 0.f, s2 = 0.f;
        #pragma unroll
        for (int g = 0; g < 16; g++) { s += s_m[g][tid]; s2 += s_v[g][tid]; }
        g_part2[blockIdx.x * 128 + tid] = s;
        g_part2[16384 + blockIdx.x * 128 + tid] = s2;
    }
}

// ---------------- K6: reduce BN2 partials in-block + BN + relu ----------------
// grid = 128 blocks, 256 threads; each block handles 128 rows.
__global__ __launch_bounds__(256) void k6_final(
    float* __restrict__ out,
    const float* __restrict__ gam2, const float* __restrict__ bet2)
{
    __shared__ float s_sc[128], s_sh[128];
    __shared__ float s_r[2][128], s_r2[2][128];

    const int tid = threadIdx.x;
    const int ch = tid & 127, half = tid >> 7;
    float s = 0.f, s2 = 0.f;
    #pragma unroll
    for (int b = half * 64; b < half * 64 + 64; b++) {
        s  += g_part2[b * 128 + ch];
        s2 += g_part2[16384 + b * 128 + ch];
    }
    s_r[half][ch] = s; s_r2[half][ch] = s2;
    __syncthreads();
    if (tid < 128) {
        const float ss  = s_r[0][tid] + s_r[1][tid];
        const float ss2 = s_r2[0][tid] + s_r2[1][tid];
        const float mean = ss * (1.f / (float)N_NODES);
        const float var  = ss2 * (1.f / (float)N_NODES) - mean * mean;
        const float sc = rsqrtf(var + EPS) * gam2[tid];
        s_sc[tid] = sc;
        s_sh[tid] = bet2[tid] - mean * sc;
    }
    __syncthreads();

    float4* o4 = (float4*)(out + (size_t)blockIdx.x * 128 * OUTC);
    #pragma unroll 4
    for (int i = tid; i < 128 * 32; i += 256) {
        const int c = (i & 31) * 4;
        float4 v = o4[i];
        v.x = fmaxf(fmaf(v.x, s_sc[c + 0], s_sh[c + 0]), 0.f);
        v.y = fmaxf(fmaf(v.y, s_sc[c + 1], s_sh[c + 1]), 0.f);
        v.z = fmaxf(fmaf(v.z, s_sc[c + 2], s_sh[c + 2]), 0.f);
        v.w = fmaxf(fmaf(v.w, s_sc[c + 3], s_sh[c + 3]), 0.f);
        o4[i] = v;
    }
}

// ---------------- launcher ----------------
extern "C" void kernel_launch(void* const* d_in, const int* in_sizes, int n_in,
                              void* d_out, int out_size)
{
    const float* x   = (const float*)d_in[0];
    const float* p   = (const float*)d_in[1];
    const int*   sid = (const int*)d_in[2];
    // d_in[3] = tid_euc (implicit arange/k grouping; unused)

    int o = 4;
    if (n_in >= 16 && in_sizes[4] == 1) o = 6;

    const float* lins_W = (const float*)d_in[o];
    const float* lins_b = (const float*)d_in[o + 1];
    const float* lin1_W = (const float*)d_in[o + 2];
    const float* lin1_b = (const float*)d_in[o + 3];
    const float* lin2_W = (const float*)d_in[o + 4];
    const float* lin2_b = (const float*)d_in[o + 5];
    const float* g1     = (const float*)d_in[o + 6];
    const float* b1     = (const float*)d_in[o + 7];
    const float* g2     = (const float*)d_in[o + 8];
    const float* b2     = (const float*)d_in[o + 9];
    float* out = (float*)d_out;

    k1_edge<<<N_NODES / 4, 256>>>(x, p, sid);
    k2_gemm<<<N_NODES / 128, 256>>>(lins_W, lins_b);
    k4_gemm<<<N_NODES / 128, 256>>>(x, lin1_W, lin2_W, lin1_b, lin2_b, g1, b1, out);
    k6_final<<<N_NODES / 128, 256>>>(out, g2, b2);
}